// round 1
// baseline (speedup 1.0000x reference)
#include <cuda_runtime.h>
#include <cuda_bf16.h>
#include <math.h>

// Problem shapes (fixed for this problem instance)
// encoded: (8, 64, 256, 256) f32   -> d_in[0]
// masks:   (8, 1, 256, 256) i32    -> d_in[1]   values 0..32
// W1:      (128, 32) f32           -> d_in[2]
// b1:      (32,) f32               -> d_in[3]
// W2:      (32, 4) f32             -> d_in[4]
// b2:      (4,) f32                -> d_in[5]
// out: vectors (8,32,64) then connections (8,4,32,32), f32, total 49152

#define BATCH 8
#define FDIM 64
#define HW 65536          // 256*256
#define SEGS 33           // ids 0..32 (segment 0 discarded)
#define NOBJ 32

// Scratch: packed uint8 masks (allowed: __device__ global array)
__device__ unsigned char g_mask8[BATCH * HW];

// ---------------------------------------------------------------------------
// Kernel 0: pack int32 masks -> uint8 (values 0..32 fit). 2MB read, 0.5MB write.
// ---------------------------------------------------------------------------
__global__ void pack_mask_kernel(const int* __restrict__ masks) {
    int i = blockIdx.x * blockDim.x + threadIdx.x;   // handles 4 ints
    const int n4 = BATCH * HW / 4;
    if (i < n4) {
        int4 v = ((const int4*)masks)[i];
        uchar4 u;
        u.x = (unsigned char)v.x;
        u.y = (unsigned char)v.y;
        u.z = (unsigned char)v.z;
        u.w = (unsigned char)v.w;
        ((uchar4*)g_mask8)[i] = u;
    }
}

// ---------------------------------------------------------------------------
// Kernel 1: segment max. One block per (b, f) plane: 65536 pixels, 256 threads.
// Per-thread privatized smem accumulator of 33 floats (stride 33 -> bank
// (lane + id) % 32, near-uniform random -> low conflicts). No atomics.
// Writes vectors[b][s-1][f] for s = 1..32 into d_out.
// ---------------------------------------------------------------------------
__global__ __launch_bounds__(256) void segmax_kernel(
    const float* __restrict__ enc, float* __restrict__ vec_out)
{
    const int bf = blockIdx.x;          // 0..511
    const int b  = bf >> 6;
    const int f  = bf & 63;

    __shared__ float acc[256 * SEGS];   // 33792 B

    const int t = threadIdx.x;
    float* a = acc + t * SEGS;
    const float NEG_INF = __int_as_float(0xff800000);
#pragma unroll
    for (int s = 0; s < SEGS; s++) a[s] = NEG_INF;

    const float4* p4 = (const float4*)(enc + (size_t)bf * HW);
    const uchar4* m4 = (const uchar4*)(g_mask8 + (size_t)b * HW);

    // 65536 pixels / (256 threads * 4-wide) = 64 iterations
#pragma unroll 4
    for (int i = 0; i < 64; i++) {
        int idx = i * 256 + t;          // coalesced float4 / uchar4
        float4 v = p4[idx];
        uchar4 m = m4[idx];
        a[m.x] = fmaxf(a[m.x], v.x);
        a[m.y] = fmaxf(a[m.y], v.y);
        a[m.z] = fmaxf(a[m.z], v.z);
        a[m.w] = fmaxf(a[m.w], v.w);
    }

    __syncthreads();

    // Reduce 256 private accumulators. Thread s (1..32) owns segment s.
    if (t >= 1 && t <= NOBJ) {
        float m = NEG_INF;
#pragma unroll 8
        for (int j = 0; j < 256; j++)
            m = fmaxf(m, acc[j * SEGS + t]);   // banks (j + s) % 32: conflict-free per step
        // vectors layout: (B, 32, F)
        vec_out[((size_t)b * NOBJ + (t - 1)) * FDIM + f] = m;
    }
}

// ---------------------------------------------------------------------------
// Kernel 2: pair MLP, algebraically reduced.
//   h[b,i,j,k] = (V W1_top)[i,k] + (V W1_bot)[j,k] + b1[k]
//   out[b,i,j,c] = sigmoid( h . W2[:,c] + b2[c] )
//   connections[b,c,j,i] = out[b,i,j,c]
// One block per batch b, 1024 threads.
// ---------------------------------------------------------------------------
__global__ __launch_bounds__(1024) void pair_mlp_kernel(
    const float* __restrict__ vec,      // (8,32,64) — vectors region of d_out
    const float* __restrict__ W1,       // (128,32)
    const float* __restrict__ b1,       // (32,)
    const float* __restrict__ W2,       // (32,4)
    const float* __restrict__ b2,       // (4,)
    float* __restrict__ conn)           // (8,4,32,32)
{
    const int b = blockIdx.x;
    const int t = threadIdx.x;

    __shared__ float sW1[128 * 32];         // 16 KB
    __shared__ float sV[32][64];            // 8 KB   (broadcast reads only)
    __shared__ float sA[32][SEGS];          // padded to 33
    __shared__ float sB[32][SEGS];
    __shared__ float sW2[32 * 4];
    __shared__ float sb2[4];

    for (int i = t; i < 128 * 32; i += 1024) sW1[i] = W1[i];
    for (int i = t; i < 32 * 64; i += 1024)  sV[i >> 6][i & 63] = vec[(size_t)b * 2048 + i];
    if (t < 128) sW2[t] = W2[t];
    if (t < 4)   sb2[t] = b2[t];
    __syncthreads();

    // Phase A: A = V @ W1[:64,:] + b1 ; B = V @ W1[64:,:]
    {
        const int i = t >> 5;          // 0..31
        const int k = t & 31;          // lane -> conflict-free sW1[d*32+k]
        float accA = b1[k];
        float accB = 0.f;
#pragma unroll 8
        for (int d = 0; d < 64; d++) {
            float v = sV[i][d];                    // broadcast within warp
            accA += v * sW1[d * 32 + k];
            accB += v * sW1[(64 + d) * 32 + k];
        }
        sA[i][k] = accA;
        sB[i][k] = accB;
    }
    __syncthreads();

    // Phase B: one thread per (i, j) pair
    {
        const int i = t >> 5;
        const int j = t & 31;          // lane -> sB[j][k] banks (j+k)%32 conflict-free
        float o0 = sb2[0], o1 = sb2[1], o2 = sb2[2], o3 = sb2[3];
#pragma unroll
        for (int k = 0; k < 32; k++) {
            float h = sA[i][k] + sB[j][k];
            o0 += h * sW2[k * 4 + 0];
            o1 += h * sW2[k * 4 + 1];
            o2 += h * sW2[k * 4 + 2];
            o3 += h * sW2[k * 4 + 3];
        }
        float* cb = conn + (size_t)b * 4096 + j * 32 + i;  // connections[b][c][j][i]
        cb[0]        = 1.f / (1.f + expf(-o0));
        cb[1024]     = 1.f / (1.f + expf(-o1));
        cb[2048]     = 1.f / (1.f + expf(-o2));
        cb[3072]     = 1.f / (1.f + expf(-o3));
    }
}

// ---------------------------------------------------------------------------
extern "C" void kernel_launch(void* const* d_in, const int* in_sizes, int n_in,
                              void* d_out, int out_size)
{
    const float* enc   = (const float*)d_in[0];
    const int*   masks = (const int*)  d_in[1];
    const float* W1    = (const float*)d_in[2];
    const float* b1    = (const float*)d_in[3];
    const float* W2    = (const float*)d_in[4];
    const float* b2    = (const float*)d_in[5];

    float* out_f = (float*)d_out;
    float* vectors = out_f;                          // 8*32*64 = 16384
    float* conn    = out_f + BATCH * NOBJ * FDIM;    // 8*4*32*32 = 32768

    // K0: pack masks to u8
    {
        const int n4 = BATCH * HW / 4;               // 131072
        pack_mask_kernel<<<(n4 + 255) / 256, 256>>>(masks);
    }
    // K1: segment max -> vectors
    segmax_kernel<<<BATCH * FDIM, 256>>>(enc, vectors);
    // K2: pair MLP -> connections
    pair_mlp_kernel<<<BATCH, 1024>>>(vectors, W1, b1, W2, b2, conn);
}

// round 2
// speedup vs baseline: 1.1867x; 1.1867x over previous
#include <cuda_runtime.h>
#include <cuda_bf16.h>
#include <math.h>

// encoded: (8, 64, 256, 256) f32   -> d_in[0]
// masks:   (8, 1, 256, 256) i32    -> d_in[1]   values 0..32
// W1: (128,32) f32, b1: (32,), W2: (32,4), b2: (4,)
// out: vectors (8,32,64) then connections (8,4,32,32), f32

#define BATCH 8
#define FDIM 64
#define HW 65536
#define SEGS 33
#define NOBJ 32

__device__ unsigned char g_mask8[BATCH * HW];

// ---------------------------------------------------------------------------
// Kernel 0: pack int32 masks -> uint8. Each thread: 4x int4 load -> 1x int4 store.
// ---------------------------------------------------------------------------
__global__ __launch_bounds__(256) void pack_mask_kernel(const int* __restrict__ masks) {
    int i = blockIdx.x * blockDim.x + threadIdx.x;   // handles 16 ints
    const int4* in4 = (const int4*)masks;
    int4 a = in4[i * 4 + 0];
    int4 b = in4[i * 4 + 1];
    int4 c = in4[i * 4 + 2];
    int4 d = in4[i * 4 + 3];
    int4 o;
    o.x = (a.x & 0xff) | ((a.y & 0xff) << 8) | ((a.z & 0xff) << 16) | (a.w << 24);
    o.y = (b.x & 0xff) | ((b.y & 0xff) << 8) | ((b.z & 0xff) << 16) | (b.w << 24);
    o.z = (c.x & 0xff) | ((c.y & 0xff) << 8) | ((c.z & 0xff) << 16) | (c.w << 24);
    o.w = (d.x & 0xff) | ((d.y & 0xff) << 8) | ((d.z & 0xff) << 16) | (d.w << 24);
    ((int4*)g_mask8)[i] = o;
}

// ---------------------------------------------------------------------------
// Kernel 1: segment max. One block per (b, f) plane, 256 threads.
// Accumulator layout acc[s*256 + t]: bank = t%32 = lane -> conflict-free for
// EVERY id value (256 % 32 == 0). No atomics, no conflicts.
// ---------------------------------------------------------------------------
__global__ __launch_bounds__(256) void segmax_kernel(
    const float* __restrict__ enc, float* __restrict__ vec_out)
{
    const int bf = blockIdx.x;          // 0..511
    const int b  = bf >> 6;
    const int f  = bf & 63;

    __shared__ float acc[SEGS * 256];   // 33792 B

    const int t = threadIdx.x;
    const float NEG_INF = __int_as_float(0xff800000);
#pragma unroll
    for (int s = 0; s < SEGS; s++) acc[s * 256 + t] = NEG_INF;
    // no __syncthreads needed: each thread only touches its own column t

    const float4* p4 = (const float4*)(enc + (size_t)bf * HW);
    const uchar4* m4 = (const uchar4*)(g_mask8 + (size_t)b * HW);

    float* ac = acc + t;                // column base

#pragma unroll 4
    for (int i = 0; i < 64; i++) {
        int idx = i * 256 + t;          // coalesced float4 / uchar4
        float4 v = p4[idx];
        uchar4 m = m4[idx];
        float* px = ac + (int)m.x * 256;  *px = fmaxf(*px, v.x);
        float* py = ac + (int)m.y * 256;  *py = fmaxf(*py, v.y);
        float* pz = ac + (int)m.z * 256;  *pz = fmaxf(*pz, v.z);
        float* pw = ac + (int)m.w * 256;  *pw = fmaxf(*pw, v.w);
    }

    __syncthreads();

    // Reduce 256 columns per segment. 8 threads per segment (s = t>>3 + 1),
    // each scans 32 entries with lane-staggered offset -> conflict-free.
    {
        const int sidx = t >> 3;            // 0..31 -> segment sidx+1
        const int k    = t & 7;
        const float* base = acc + (sidx + 1) * 256 + k * 32;
        float m = NEG_INF;
#pragma unroll
        for (int i = 0; i < 32; i++) {
            int j = (i + t) & 31;           // bank = (i+t)%32, distinct per lane
            m = fmaxf(m, base[j]);
        }
        // reduce the 8 partials (consecutive lanes) via width-8 shuffles
        m = fmaxf(m, __shfl_down_sync(0xffffffffu, m, 4, 8));
        m = fmaxf(m, __shfl_down_sync(0xffffffffu, m, 2, 8));
        m = fmaxf(m, __shfl_down_sync(0xffffffffu, m, 1, 8));
        if (k == 0)
            vec_out[((size_t)b * NOBJ + sidx) * FDIM + f] = m;
    }
}

// ---------------------------------------------------------------------------
// Kernel 2: pair MLP, algebraically reduced.
//   h[b,i,j,k] = (V W1_top)[i,k] + (V W1_bot)[j,k] + b1[k]
//   connections[b,c,j,i] = sigmoid(h . W2[:,c] + b2[c])
// ---------------------------------------------------------------------------
__global__ __launch_bounds__(1024) void pair_mlp_kernel(
    const float* __restrict__ vec, const float* __restrict__ W1,
    const float* __restrict__ b1, const float* __restrict__ W2,
    const float* __restrict__ b2, float* __restrict__ conn)
{
    const int b = blockIdx.x;
    const int t = threadIdx.x;

    __shared__ float sW1[128 * 32];
    __shared__ float sV[32][64];
    __shared__ float sA[32][SEGS];
    __shared__ float sB[32][SEGS];
    __shared__ float sW2[32 * 4];
    __shared__ float sb2[4];

    for (int i = t; i < 128 * 32; i += 1024) sW1[i] = W1[i];
    for (int i = t; i < 32 * 64; i += 1024)  sV[i >> 6][i & 63] = vec[(size_t)b * 2048 + i];
    if (t < 128) sW2[t] = W2[t];
    if (t < 4)   sb2[t] = b2[t];
    __syncthreads();

    {
        const int i = t >> 5;
        const int k = t & 31;
        float accA = b1[k];
        float accB = 0.f;
#pragma unroll 8
        for (int d = 0; d < 64; d++) {
            float v = sV[i][d];
            accA += v * sW1[d * 32 + k];
            accB += v * sW1[(64 + d) * 32 + k];
        }
        sA[i][k] = accA;
        sB[i][k] = accB;
    }
    __syncthreads();

    {
        const int i = t >> 5;
        const int j = t & 31;
        float o0 = sb2[0], o1 = sb2[1], o2 = sb2[2], o3 = sb2[3];
#pragma unroll
        for (int k = 0; k < 32; k++) {
            float h = sA[i][k] + sB[j][k];
            o0 += h * sW2[k * 4 + 0];
            o1 += h * sW2[k * 4 + 1];
            o2 += h * sW2[k * 4 + 2];
            o3 += h * sW2[k * 4 + 3];
        }
        float* cb = conn + (size_t)b * 4096 + j * 32 + i;
        cb[0]    = 1.f / (1.f + expf(-o0));
        cb[1024] = 1.f / (1.f + expf(-o1));
        cb[2048] = 1.f / (1.f + expf(-o2));
        cb[3072] = 1.f / (1.f + expf(-o3));
    }
}

// ---------------------------------------------------------------------------
extern "C" void kernel_launch(void* const* d_in, const int* in_sizes, int n_in,
                              void* d_out, int out_size)
{
    const float* enc   = (const float*)d_in[0];
    const int*   masks = (const int*)  d_in[1];
    const float* W1    = (const float*)d_in[2];
    const float* b1    = (const float*)d_in[3];
    const float* W2    = (const float*)d_in[4];
    const float* b2    = (const float*)d_in[5];

    float* out_f = (float*)d_out;
    float* vectors = out_f;
    float* conn    = out_f + BATCH * NOBJ * FDIM;

    // K0: pack masks (8*65536 ints / 16 per thread = 32768 threads)
    pack_mask_kernel<<<128, 256>>>(masks);
    // K1: segment max -> vectors
    segmax_kernel<<<BATCH * FDIM, 256>>>(enc, vectors);
    // K2: pair MLP -> connections
    pair_mlp_kernel<<<BATCH, 1024>>>(vectors, W1, b1, W2, b2, conn);
}

// round 3
// speedup vs baseline: 1.2266x; 1.0336x over previous
#include <cuda_runtime.h>
#include <cuda_bf16.h>
#include <math.h>

// encoded: (8, 64, 256, 256) f32, masks: (8,1,256,256) i32 (0..32)
// W1: (128,32), b1: (32,), W2: (32,4), b2: (4,)
// out: vectors (8,32,64) ++ connections (8,4,32,32)

#define BATCH 8
#define FDIM 64
#define HW 65536
#define SEGS 33
#define NOBJ 32

__device__ unsigned char g_mask8[BATCH * HW];
__device__ float g_sink;

// ---------------------------------------------------------------------------
// K0: pack int32 masks -> uint8. 1 int4 -> 1 uint per thread; 131072 threads.
// Also warms L2 with the MLP weights (W1: 16KB, W2+biases tiny).
// ---------------------------------------------------------------------------
__global__ __launch_bounds__(256) void pack_mask_kernel(
    const int* __restrict__ masks, const float* __restrict__ W1,
    const float* __restrict__ W2)
{
    int i = blockIdx.x * blockDim.x + threadIdx.x;     // 1 int4 = 4 ints
    int4 v = ((const int4*)masks)[i];
    unsigned int o = (v.x & 0xff) | ((v.y & 0xff) << 8) |
                     ((v.z & 0xff) << 16) | (v.w << 24);
    ((unsigned int*)g_mask8)[i] = o;

    // L2 warm for MLP weights (one block's worth of touches)
    if (blockIdx.x == 0) {
        float w = W1[threadIdx.x * 16] + W2[threadIdx.x & 127];
        if (w == 1234.56789f) g_sink = w;   // never true; keeps the loads
    }
}

// ---------------------------------------------------------------------------
// K1: segment max, 2 f-planes per block with float2 accumulators.
// Block bf: b = bf>>5, planes f0 = bf&31 and f0+32. 256 threads.
// acc2[s*256 + t]: 64-bit accesses, lane-indexed -> conflict-free (2-phase
// inherent to LDS.64). Halves chains/instructions vs 1-plane version.
// ---------------------------------------------------------------------------
__global__ __launch_bounds__(256) void segmax_kernel(
    const float* __restrict__ enc, float* __restrict__ vec_out)
{
    extern __shared__ float2 acc2[];        // SEGS*256 float2 = 67584 B

    const int bf = blockIdx.x;              // 0..255
    const int b  = bf >> 5;
    const int f0 = bf & 31;                 // planes f0 and f0+32

    const int t = threadIdx.x;
    const float NEG_INF = __int_as_float(0xff800000);
#pragma unroll
    for (int s = 0; s < SEGS; s++) acc2[s * 256 + t] = make_float2(NEG_INF, NEG_INF);
    // each thread touches only its own column t -> no sync needed

    const float4* p0 = (const float4*)(enc + ((size_t)b * FDIM + f0) * HW);
    const float4* p1 = (const float4*)(enc + ((size_t)b * FDIM + f0 + 32) * HW);
    const uchar4* m4 = (const uchar4*)(g_mask8 + (size_t)b * HW);

    float2* ac = acc2 + t;

#pragma unroll 4
    for (int i = 0; i < 64; i++) {
        int idx = i * 256 + t;
        float4 v0 = p0[idx];
        float4 v1 = p1[idx];
        uchar4 m  = m4[idx];
        float2* px = ac + (int)m.x * 256;
        float2* py = ac + (int)m.y * 256;
        float2* pz = ac + (int)m.z * 256;
        float2* pw = ac + (int)m.w * 256;
        float2 ax = *px; ax.x = fmaxf(ax.x, v0.x); ax.y = fmaxf(ax.y, v1.x); *px = ax;
        float2 ay = *py; ay.x = fmaxf(ay.x, v0.y); ay.y = fmaxf(ay.y, v1.y); *py = ay;
        float2 az = *pz; az.x = fmaxf(az.x, v0.z); az.y = fmaxf(az.y, v1.z); *pz = az;
        float2 aw = *pw; aw.x = fmaxf(aw.x, v0.w); aw.y = fmaxf(aw.y, v1.w); *pw = aw;
    }

    __syncthreads();

    // Reduce 256 columns per segment: 8 threads per segment, lane-staggered.
    {
        const int sidx = t >> 3;            // 0..31 -> segment sidx+1
        const int k    = t & 7;
        const float2* base = acc2 + (sidx + 1) * 256 + k * 32;
        float mx = NEG_INF, my = NEG_INF;
#pragma unroll
        for (int i = 0; i < 32; i++) {
            int j = (i + t) & 31;
            float2 v = base[j];
            mx = fmaxf(mx, v.x);
            my = fmaxf(my, v.y);
        }
        mx = fmaxf(mx, __shfl_down_sync(0xffffffffu, mx, 4, 8));
        mx = fmaxf(mx, __shfl_down_sync(0xffffffffu, mx, 2, 8));
        mx = fmaxf(mx, __shfl_down_sync(0xffffffffu, mx, 1, 8));
        my = fmaxf(my, __shfl_down_sync(0xffffffffu, my, 4, 8));
        my = fmaxf(my, __shfl_down_sync(0xffffffffu, my, 2, 8));
        my = fmaxf(my, __shfl_down_sync(0xffffffffu, my, 1, 8));
        if (k == 0) {
            float* vrow = vec_out + ((size_t)b * NOBJ + sidx) * FDIM;
            vrow[f0]      = mx;
            vrow[f0 + 32] = my;
        }
    }
}

// ---------------------------------------------------------------------------
// K2: pair MLP (algebraically reduced).
//   h[b,i,j,k] = (V W1_top)[i,k] + (V W1_bot)[j,k] + b1[k]
//   connections[b,c,j,i] = sigmoid(h . W2[:,c] + b2[c])
// ---------------------------------------------------------------------------
__global__ __launch_bounds__(1024) void pair_mlp_kernel(
    const float* __restrict__ vec, const float* __restrict__ W1,
    const float* __restrict__ b1, const float* __restrict__ W2,
    const float* __restrict__ b2, float* __restrict__ conn)
{
    const int b = blockIdx.x;
    const int t = threadIdx.x;

    __shared__ float sW1[128 * 32];
    __shared__ float sV[32][64];
    __shared__ float sA[32][SEGS];
    __shared__ float sB[32][SEGS];
    __shared__ float sW2[32 * 4];
    __shared__ float sb2[4];

    for (int i = t; i < 128 * 32; i += 1024) sW1[i] = W1[i];
    for (int i = t; i < 32 * 64; i += 1024)  sV[i >> 6][i & 63] = vec[(size_t)b * 2048 + i];
    if (t < 128) sW2[t] = W2[t];
    if (t < 4)   sb2[t] = b2[t];
    __syncthreads();

    {
        const int i = t >> 5;
        const int k = t & 31;
        float accA = b1[k];
        float accB = 0.f;
#pragma unroll 8
        for (int d = 0; d < 64; d++) {
            float v = sV[i][d];
            accA += v * sW1[d * 32 + k];
            accB += v * sW1[(64 + d) * 32 + k];
        }
        sA[i][k] = accA;
        sB[i][k] = accB;
    }
    __syncthreads();

    {
        const int i = t >> 5;
        const int j = t & 31;
        float o0 = sb2[0], o1 = sb2[1], o2 = sb2[2], o3 = sb2[3];
#pragma unroll
        for (int k = 0; k < 32; k++) {
            float h = sA[i][k] + sB[j][k];
            o0 += h * sW2[k * 4 + 0];
            o1 += h * sW2[k * 4 + 1];
            o2 += h * sW2[k * 4 + 2];
            o3 += h * sW2[k * 4 + 3];
        }
        float* cb = conn + (size_t)b * 4096 + j * 32 + i;
        cb[0]    = 1.f / (1.f + expf(-o0));
        cb[1024] = 1.f / (1.f + expf(-o1));
        cb[2048] = 1.f / (1.f + expf(-o2));
        cb[3072] = 1.f / (1.f + expf(-o3));
    }
}

// ---------------------------------------------------------------------------
extern "C" void kernel_launch(void* const* d_in, const int* in_sizes, int n_in,
                              void* d_out, int out_size)
{
    const float* enc   = (const float*)d_in[0];
    const int*   masks = (const int*)  d_in[1];
    const float* W1    = (const float*)d_in[2];
    const float* b1    = (const float*)d_in[3];
    const float* W2    = (const float*)d_in[4];
    const float* b2    = (const float*)d_in[5];

    float* out_f = (float*)d_out;
    float* vectors = out_f;
    float* conn    = out_f + BATCH * NOBJ * FDIM;

    static bool attr_done = false;
    if (!attr_done) {
        cudaFuncSetAttribute(segmax_kernel,
                             cudaFuncAttributeMaxDynamicSharedMemorySize,
                             SEGS * 256 * (int)sizeof(float2));
        attr_done = true;
    }

    // K0: pack masks (524288 ints / 4 per thread = 131072 threads) + L2 warm
    pack_mask_kernel<<<512, 256>>>(masks, W1, W2);
    // K1: segment max, 2 planes per block
    segmax_kernel<<<BATCH * 32, 256, SEGS * 256 * sizeof(float2)>>>(enc, vectors);
    // K2: pair MLP
    pair_mlp_kernel<<<BATCH, 1024>>>(vectors, W1, b1, W2, b2, conn);
}